// round 5
// baseline (speedup 1.0000x reference)
#include <cuda_runtime.h>

#define TT   512
#define HH   50
#define NTHR 128

typedef unsigned long long u64;

__device__ __forceinline__ u64 pack2(float x) {
    u64 r; asm("mov.b64 %0, {%1,%1};" : "=l"(r) : "f"(x)); return r;
}
__device__ __forceinline__ u64 packpair(float a, float b) {
    u64 r; asm("mov.b64 %0, {%1,%2};" : "=l"(r) : "f"(a), "f"(b)); return r;
}
__device__ __forceinline__ u64 fma2(u64 a, u64 b, u64 c) {
    u64 d; asm("fma.rn.f32x2 %0, %1, %2, %3;" : "=l"(d) : "l"(a), "l"(b), "l"(c)); return d;
}
__device__ __forceinline__ void unpk(u64 v, float& lo, float& hi) {
    asm("mov.b64 {%0, %1}, %2;" : "=f"(lo), "=f"(hi) : "l"(v));
}
__device__ __forceinline__ u64 bfly64(u64 v, unsigned m) {
    unsigned lo, hi;
    asm("mov.b64 {%0, %1}, %2;" : "=r"(lo), "=r"(hi) : "l"(v));
    lo = __shfl_xor_sync(m, lo, 1);
    hi = __shfl_xor_sync(m, hi, 1);
    u64 r; asm("mov.b64 %0, {%1, %2};" : "=l"(r) : "r"(lo), "r"(hi));
    return r;
}
__device__ __forceinline__ float tanhap(float x) {
    float y; asm("tanh.approx.f32 %0, %1;" : "=f"(y) : "f"(x)); return y;
}
__device__ __forceinline__ float sigap(float x) {
    return fmaf(tanhap(0.5f * x), 0.5f, 0.5f);
}

// NP = cells per active thread; NB = 2*NP batches per block.
// f32x2 lanes hold the thread's TWO GATE ROWS (r0, r1); accumulators are
// per-batch. Weights pre-packed as (w_r0[k], w_r1[k]) u64 pairs in registers.
// h and x are stored DUPLICATED in shared so they broadcast-load as f32x2.
template<int NP>
__device__ __forceinline__ void run_lstm(
    u64 (*xd)[8], u64 (*hd)[HH][8], int b0, int tid,
    const float* __restrict__ x,    const float* __restrict__ W_ih,
    const float* __restrict__ W_hh, const float* __restrict__ b_ih,
    const float* __restrict__ b_hh, const float* __restrict__ fc_w,
    const float* __restrict__ fc_b, float* __restrict__ out)
{
    constexpr int NB = 2 * NP;

    // ---- stage x: global [b][t] -> shared dup [t][b] (u64 pairs) ----
    const float4* xg = reinterpret_cast<const float4*>(x);
    for (int idx = tid; idx < NB * 128; idx += NTHR) {
        int bb = idx >> 7, t4 = idx & 127;
        float4 v = xg[(size_t)(b0 + bb) * 128 + t4];
        int t = t4 * 4;
        xd[t + 0][bb] = pack2(v.x); xd[t + 1][bb] = pack2(v.y);
        xd[t + 2][bb] = pack2(v.z); xd[t + 3][bb] = pack2(v.w);
    }
    for (int i = tid; i < 2 * HH * 8; i += NTHR) (&hd[0][0][0])[i] = 0ULL;

    // ---- row mapping: even tid=2j -> rows (j: i-gate, j+100: g-gate)
    //                   odd  tid=2j+1 -> rows (j+50: f-gate, j+150: o-gate)
    const bool act = (tid < 2 * HH);
    const int  j   = tid >> 1;
    const int  r0  = (tid & 1) ? (j + HH) : j;
    const int  r1  = r0 + 2 * HH;

    u64 wpk[HH];
    u64 wxp = 0, bip = 0;
    if (act) {
        #pragma unroll
        for (int k = 0; k < HH; k++)
            wpk[k] = packpair(W_hh[r0 * HH + k], W_hh[r1 * HH + k]);
        wxp = packpair(W_ih[r0], W_ih[r1]);
        bip = packpair(b_ih[r0] + b_hh[r0], b_ih[r1] + b_hh[r1]);
    }
    float c[NP];
    #pragma unroll
    for (int p = 0; p < NP; p++) c[p] = 0.f;

    __syncthreads();

    #pragma unroll 1
    for (int t = 0; t < TT; t++) {
        if (act) {
            // ===== gate phase: A[b] = (gate_r0(b), gate_r1(b)) =====
            u64 A[NB];
            #pragma unroll
            for (int b = 0; b < NB; b += 2) {
                ulonglong2 q = *reinterpret_cast<const ulonglong2*>(&xd[t][b]);
                A[b]     = fma2(q.x, wxp, bip);
                A[b + 1] = fma2(q.y, wxp, bip);
            }
            const u64* hs = &hd[t & 1][0][0];
            #pragma unroll
            for (int k = 0; k < HH; k++) {
                u64 wp = wpk[k];
                #pragma unroll
                for (int b = 0; b < NB; b += 2) {
                    ulonglong2 q = *reinterpret_cast<const ulonglong2*>(hs + k * 8 + b);
                    A[b]     = fma2(q.x, wp, A[b]);
                    A[b + 1] = fma2(q.y, wp, A[b + 1]);
                }
            }

            // ===== exchange: even keeps batches [0,NP), odd keeps [NP,NB) =====
            unsigned m = __activemask();
            bool ev = !(tid & 1);
            u64 S[NP];
            #pragma unroll
            for (int p = 0; p < NP; p++)
                S[p] = bfly64(ev ? A[p + NP] : A[p], m);

            // ===== cell update: NP cells (unit j, batches bb0..bb0+NP-1) =====
            float hn[NP];
            #pragma unroll
            for (int p = 0; p < NP; p++) {
                u64 IG = ev ? A[p] : S[p];          // (i, g) for this batch
                u64 FO = ev ? S[p] : A[p + NP];     // (f, o)
                float iv, gv, fv, ov;
                unpk(IG, iv, gv);
                unpk(FO, fv, ov);
                c[p]  = sigap(fv) * c[p] + sigap(iv) * tanhap(gv);
                hn[p] = sigap(ov) * tanhap(c[p]);
            }
            u64* hw = &hd[(t + 1) & 1][j][ev ? 0 : NP];
            #pragma unroll
            for (int p = 0; p < NP; p++) hw[p] = pack2(hn[p]);
        }
        __syncthreads();
    }

    // ===== final FC on h_T (buffer 0 since TT is even; read lo lane) =====
    if (tid < NB * 3) {
        int bb = tid / 3, o = tid % 3;
        float s = fc_b[o];
        #pragma unroll
        for (int k = 0; k < HH; k++)
            s += *reinterpret_cast<const float*>(&hd[0][k][bb]) * fc_w[o * HH + k];
        out[(size_t)(b0 + bb) * 3 + o] = s;
    }
}

__global__ void __launch_bounds__(NTHR, 2)
lstm_fused(const float* __restrict__ x,    const float* __restrict__ W_ih,
           const float* __restrict__ W_hh, const float* __restrict__ b_ih,
           const float* __restrict__ b_hh, const float* __restrict__ fc_w,
           const float* __restrict__ fc_b, float* __restrict__ out)
{
    __shared__ __align__(16) u64 xd[TT][8];        // 32 KB, x duplicated pairs
    __shared__ __align__(16) u64 hd[2][HH][8];     // 6.4 KB, h duplicated pairs
    const int bid = blockIdx.x;
    // LUT_classic[bid % 148]: bid and bid+148 share an SM. Pair one 8-batch
    // block with one 6-batch block per SM -> even per-SM load (14 batches).
    if (bid < 148) {
        run_lstm<4>(xd, hd, bid * 8, threadIdx.x,
                    x, W_ih, W_hh, b_ih, b_hh, fc_w, fc_b, out);
    } else {
        run_lstm<3>(xd, hd, 1184 + (bid - 148) * 6, threadIdx.x,
                    x, W_ih, W_hh, b_ih, b_hh, fc_w, fc_b, out);
    }
}

extern "C" void kernel_launch(void* const* d_in, const int* in_sizes, int n_in,
                              void* d_out, int out_size) {
    const float* x    = (const float*)d_in[0];
    const float* W_ih = (const float*)d_in[1];
    const float* W_hh = (const float*)d_in[2];
    const float* b_ih = (const float*)d_in[3];
    const float* b_hh = (const float*)d_in[4];
    const float* fc_w = (const float*)d_in[5];
    const float* fc_b = (const float*)d_in[6];
    lstm_fused<<<292, NTHR>>>(x, W_ih, W_hh, b_ih, b_hh, fc_w, fc_b, (float*)d_out);
}

// round 6
// speedup vs baseline: 1.3080x; 1.3080x over previous
#include <cuda_runtime.h>

#define TT   512
#define HH   50
#define NTHR 128

typedef unsigned long long u64;

__device__ __forceinline__ u64 pack2(float x) {
    u64 r; asm("mov.b64 %0, {%1,%1};" : "=l"(r) : "f"(x)); return r;
}
__device__ __forceinline__ u64 fma2(u64 a, u64 b, u64 c) {
    u64 d; asm("fma.rn.f32x2 %0, %1, %2, %3;" : "=l"(d) : "l"(a), "l"(b), "l"(c)); return d;
}
__device__ __forceinline__ void unpk(u64 v, float& lo, float& hi) {
    asm("mov.b64 {%0, %1}, %2;" : "=f"(lo), "=f"(hi) : "l"(v));
}
__device__ __forceinline__ u64 bfly64(u64 v, unsigned m) {
    unsigned lo, hi;
    asm("mov.b64 {%0, %1}, %2;" : "=r"(lo), "=r"(hi) : "l"(v));
    lo = __shfl_xor_sync(m, lo, 1);
    hi = __shfl_xor_sync(m, hi, 1);
    u64 r; asm("mov.b64 %0, {%1, %2};" : "=l"(r) : "r"(lo), "r"(hi));
    return r;
}
__device__ __forceinline__ float tanhap(float x) {
    float y; asm("tanh.approx.f32 %0, %1;" : "=f"(y) : "f"(x)); return y;
}
__device__ __forceinline__ float sigap(float x) {
    return fmaf(tanhap(0.5f * x), 0.5f, 0.5f);
}

// Two batch groups per block: A = 4 batches, B = 2*NPB batches (NPB=2 heavy, 1 light).
// Separate h buffers + separate k-loops let group A's update MUFUs hide under
// group B's FFMA2 stream (software pipelining within the thread).
template<int NPB>
__device__ __forceinline__ void run_lstm(
    float (*x_sh)[8], float (*hA)[HH][4], float (*hB)[HH][4], int b0, int tid,
    const float* __restrict__ x,    const float* __restrict__ W_ih,
    const float* __restrict__ W_hh, const float* __restrict__ b_ih,
    const float* __restrict__ b_hh, const float* __restrict__ fc_w,
    const float* __restrict__ fc_b, float* __restrict__ out)
{
    constexpr int NB = 4 + 2 * NPB;

    // ---- stage x: global [b][t] -> shared [t][b] ----
    const float4* xg = reinterpret_cast<const float4*>(x);
    for (int idx = tid; idx < NB * 128; idx += NTHR) {
        int bb = idx >> 7, t4 = idx & 127;
        float4 v = xg[(size_t)(b0 + bb) * 128 + t4];
        int t = t4 * 4;
        x_sh[t + 0][bb] = v.x; x_sh[t + 1][bb] = v.y;
        x_sh[t + 2][bb] = v.z; x_sh[t + 3][bb] = v.w;
    }
    for (int i = tid; i < 2 * HH * 4; i += NTHR) {
        (&hA[0][0][0])[i] = 0.f;
        (&hB[0][0][0])[i] = 0.f;
    }

    // ---- row mapping: even tid=2j -> rows (j: i-gate, j+100: g-gate)
    //                   odd  tid=2j+1 -> rows (j+50: f-gate, j+150: o-gate)
    const bool act = (tid < 2 * HH);
    const int  j   = tid >> 1;
    const int  r0  = (tid & 1) ? (j + HH) : j;
    const int  r1  = r0 + 2 * HH;

    float w0[HH], w1[HH];
    u64 wx0 = 0, wx1 = 0, bi0 = 0, bi1 = 0;
    if (act) {
        #pragma unroll
        for (int k = 0; k < HH; k++) {
            w0[k] = W_hh[r0 * HH + k];
            w1[k] = W_hh[r1 * HH + k];
        }
        wx0 = pack2(W_ih[r0]);
        wx1 = pack2(W_ih[r1]);
        bi0 = pack2(b_ih[r0] + b_hh[r0]);
        bi1 = pack2(b_ih[r1] + b_hh[r1]);
    }
    float cA0 = 0.f, cA1 = 0.f;
    float cB0 = 0.f, cB1 = 0.f;

    __syncthreads();

    #pragma unroll 1
    for (int t = 0; t < TT; t++) {
        if (act) {
            unsigned m = __activemask();
            bool ev = !(tid & 1);
            const int rb = t & 1, wb = (t + 1) & 1;

            // ===== gate A (batches 0-3) =====
            ulonglong2 xqA = *reinterpret_cast<const ulonglong2*>(&x_sh[t][0]);
            u64 A00 = fma2(xqA.x, wx0, bi0);
            u64 A01 = fma2(xqA.y, wx0, bi0);
            u64 A10 = fma2(xqA.x, wx1, bi1);
            u64 A11 = fma2(xqA.y, wx1, bi1);
            {
                const float* hs = &hA[rb][0][0];
                #pragma unroll
                for (int k = 0; k < HH; k++) {
                    ulonglong2 q = *reinterpret_cast<const ulonglong2*>(hs + k * 4);
                    u64 w0p = pack2(w0[k]);
                    u64 w1p = pack2(w1[k]);
                    A00 = fma2(q.x, w0p, A00);
                    A01 = fma2(q.y, w0p, A01);
                    A10 = fma2(q.x, w1p, A10);
                    A11 = fma2(q.y, w1p, A11);
                }
            }
            // exchange + update A (MUFUs — scheduler sinks these into gate B)
            u64 sA0 = bfly64(ev ? A01 : A00, m);
            u64 sA1 = bfly64(ev ? A11 : A10, m);
            float iv0, iv1, gv0, gv1, fv0, fv1, ov0, ov1;
            unpk(ev ? A00 : sA0, iv0, iv1);
            unpk(ev ? A10 : sA1, gv0, gv1);
            unpk(ev ? sA0 : A01, fv0, fv1);
            unpk(ev ? sA1 : A11, ov0, ov1);
            cA0 = sigap(fv0) * cA0 + sigap(iv0) * tanhap(gv0);
            cA1 = sigap(fv1) * cA1 + sigap(iv1) * tanhap(gv1);
            float hA0 = sigap(ov0) * tanhap(cA0);
            float hA1 = sigap(ov1) * tanhap(cA1);

            // ===== gate B (batches 4..4+2*NPB-1) =====
            u64 B00, B01, B10, B11;
            if (NPB == 2) {
                ulonglong2 xqB = *reinterpret_cast<const ulonglong2*>(&x_sh[t][4]);
                B00 = fma2(xqB.x, wx0, bi0);
                B01 = fma2(xqB.y, wx0, bi0);
                B10 = fma2(xqB.x, wx1, bi1);
                B11 = fma2(xqB.y, wx1, bi1);
                const float* hs = &hB[rb][0][0];
                #pragma unroll
                for (int k = 0; k < HH; k++) {
                    ulonglong2 q = *reinterpret_cast<const ulonglong2*>(hs + k * 4);
                    u64 w0p = pack2(w0[k]);
                    u64 w1p = pack2(w1[k]);
                    B00 = fma2(q.x, w0p, B00);
                    B01 = fma2(q.y, w0p, B01);
                    B10 = fma2(q.x, w1p, B10);
                    B11 = fma2(q.y, w1p, B11);
                }
            } else {
                u64 xqB = *reinterpret_cast<const u64*>(&x_sh[t][4]);
                B00 = fma2(xqB, wx0, bi0);
                B10 = fma2(xqB, wx1, bi1);
                B01 = B11 = 0;
                const float* hs = &hB[rb][0][0];
                #pragma unroll
                for (int k = 0; k < HH; k++) {
                    u64 q = *reinterpret_cast<const u64*>(hs + k * 4);
                    u64 w0p = pack2(w0[k]);
                    u64 w1p = pack2(w1[k]);
                    B00 = fma2(q, w0p, B00);
                    B10 = fma2(q, w1p, B10);
                }
            }

            // store h(A) AFTER gate B so A's MUFUs had the whole loop to finish
            float* hwA = &hA[wb][j][ev ? 0 : 2];
            hwA[0] = hA0; hwA[1] = hA1;

            // exchange + update B
            if (NPB == 2) {
                u64 sB0 = bfly64(ev ? B01 : B00, m);
                u64 sB1 = bfly64(ev ? B11 : B10, m);
                float i0, i1, g0, g1, f0, f1, o0, o1;
                unpk(ev ? B00 : sB0, i0, i1);
                unpk(ev ? B10 : sB1, g0, g1);
                unpk(ev ? sB0 : B01, f0, f1);
                unpk(ev ? sB1 : B11, o0, o1);
                cB0 = sigap(f0) * cB0 + sigap(i0) * tanhap(g0);
                cB1 = sigap(f1) * cB1 + sigap(i1) * tanhap(g1);
                float* hwB = &hB[wb][j][ev ? 0 : 2];
                hwB[0] = sigap(o0) * tanhap(cB0);
                hwB[1] = sigap(o1) * tanhap(cB1);
            } else {
                u64 sB0 = bfly64(B00, m);   // even rx (f pair), odd rx (i pair)
                u64 sB1 = bfly64(B10, m);   // even rx (o pair), odd rx (g pair)
                float iv, gv, fv, ov, d0, d1;
                if (ev) { unpk(B00, iv, d0); unpk(B10, gv, d1); unpk(sB0, fv, d0); unpk(sB1, ov, d1); }
                else    { unpk(sB0, d0, iv); unpk(sB1, d0, gv); unpk(B00, d1, fv); unpk(B10, d1, ov); }
                cB0 = sigap(fv) * cB0 + sigap(iv) * tanhap(gv);
                hB[wb][j][ev ? 0 : 1] = sigap(ov) * tanhap(cB0);
            }
        }
        __syncthreads();
    }

    // ===== final FC on h_T (buffer 0 since TT is even) =====
    if (tid < NB * 3) {
        int bb = tid / 3, o = tid % 3;
        float s = fc_b[o];
        #pragma unroll
        for (int k = 0; k < HH; k++) {
            float hv = (bb < 4) ? hA[0][k][bb] : hB[0][k][bb - 4];
            s += hv * fc_w[o * HH + k];
        }
        out[(size_t)(b0 + bb) * 3 + o] = s;
    }
}

__global__ void __launch_bounds__(NTHR, 2)
lstm_fused(const float* __restrict__ x,    const float* __restrict__ W_ih,
           const float* __restrict__ W_hh, const float* __restrict__ b_ih,
           const float* __restrict__ b_hh, const float* __restrict__ fc_w,
           const float* __restrict__ fc_b, float* __restrict__ out)
{
    __shared__ __align__(16) float x_sh[TT][8];       // 16 KB
    __shared__ __align__(16) float hA[2][HH][4];
    __shared__ __align__(16) float hB[2][HH][4];
    const int bid = blockIdx.x;
    // LUT_classic[bid % 148]: bid and bid+148 share an SM. Pair one 8-batch
    // block with one 6-batch block per SM -> even per-SM load (14 batches).
    if (bid < 148) {
        run_lstm<2>(x_sh, hA, hB, bid * 8, threadIdx.x,
                    x, W_ih, W_hh, b_ih, b_hh, fc_w, fc_b, out);
    } else {
        run_lstm<1>(x_sh, hA, hB, 1184 + (bid - 148) * 6, threadIdx.x,
                    x, W_ih, W_hh, b_ih, b_hh, fc_w, fc_b, out);
    }
}

extern "C" void kernel_launch(void* const* d_in, const int* in_sizes, int n_in,
                              void* d_out, int out_size) {
    const float* x    = (const float*)d_in[0];
    const float* W_ih = (const float*)d_in[1];
    const float* W_hh = (const float*)d_in[2];
    const float* b_ih = (const float*)d_in[3];
    const float* b_hh = (const float*)d_in[4];
    const float* fc_w = (const float*)d_in[5];
    const float* fc_b = (const float*)d_in[6];
    lstm_fused<<<292, NTHR>>>(x, W_ih, W_hh, b_ih, b_hh, fc_w, fc_b, (float*)d_out);
}